// round 10
// baseline (speedup 1.0000x reference)
#include <cuda_runtime.h>
#include <math.h>

#define B_   8
#define N_   2000
#define T_   8
#define F_   128
#define DEG_ 8
#define H_   4
#define D1_  64
#define D2_  64
#define G_   64
#define PW_  16
#define BT_  (B_*T_)     // 64
#define SEQ_ (N_*T_)     // 16000
#define HD_  (H_*D1_)    // 256

// -------- scratch (static device arrays are the sanctioned scratch path) --------
__device__ float g_z1  [(size_t)BT_*N_*HD_];            // 131 MB
__device__ float g_h1  [(size_t)BT_*N_*HD_];            // 131 MB
__device__ float g_z2  [(size_t)BT_*N_*D2_];            // 33 MB
__device__ float g_seqT[(size_t)SEQ_*B_*D2_];           // 33 MB  (xs layout: [s][b][d])
__device__ float g_gi  [(size_t)SEQ_*B_*3*G_ + 8192];   // 98 MB + prefetch pad
__device__ float g_ssrc1[BT_*H_*N_];
__device__ float g_sdst1[BT_*H_*N_];
__device__ float g_ssrc2[BT_*N_];
__device__ float g_sdst2[BT_*N_];
__device__ float g_hloc[(size_t)N_*B_*G_];              // [n][b][g]
__device__ float g_W1cat[F_*HD_];                       // [f][h*64+d]
__device__ float g_WihT [D2_*3*G_];                     // [d][j]

// ---------------------------------------------------------------------------
// sigmoid: EX2 + RCP.approx (saturates cleanly at +/-inf, no NaN, no IEEE div)
__device__ __forceinline__ float sigmoid_fast(float x)
{
    float e = __expf(-x);
    float inv;
    asm("rcp.approx.f32 %0, %1;" : "=f"(inv) : "f"(1.0f + e));
    return inv;
}

// ---------------------------------------------------------------------------
// Pack W1 -> [F, H*D1] and Wih -> [D2, 3G]
__global__ void pack_kernel(const float* __restrict__ W1, const float* __restrict__ Wih)
{
    int i = blockIdx.x * 256 + threadIdx.x;
    if (i < F_*HD_) {
        int f = i / HD_, c = i % HD_;
        int h = c >> 6, d = c & 63;
        g_W1cat[i] = W1[((size_t)h*F_ + f)*D1_ + d];
    }
    if (i < D2_*3*G_) {
        int d = i / (3*G_), j = i % (3*G_);
        g_WihT[i] = Wih[(size_t)j*D2_ + d];
    }
}

// ---------------------------------------------------------------------------
// Tiled SGEMM (scalar FFMA — known-good): C[z] = A[z] (MxK) * Bm (KxN) + bias.
// BM=128 BN=64 BK=16, 8x4 microtile.
__global__ void __launch_bounds__(256)
gemm_bias(const float* __restrict__ A, const float* __restrict__ Bm,
          const float* __restrict__ bias, float* __restrict__ C,
          int M, int N, int K, int lda, int ldc,
          long aOuter, long aInner, int innerCnt, long cStride)
{
    __shared__ float As[16][128];
    __shared__ float Bs[16][64];

    int z = blockIdx.z;
    const float* Ab = A + (long)(z / innerCnt) * aOuter + (long)(z % innerCnt) * aInner;
    float* Cb = C + (long)z * cStride;
    int m0 = blockIdx.x * 128;
    int n0 = blockIdx.y * 64;
    int tid = threadIdx.x;
    int tx = tid & 15;          // col group  (4 cols)
    int ty = tid >> 4;          // row group  (8 rows)

    float acc[8][4];
#pragma unroll
    for (int i = 0; i < 8; i++)
#pragma unroll
        for (int j = 0; j < 4; j++) acc[i][j] = 0.f;

    for (int k0 = 0; k0 < K; k0 += 16) {
#pragma unroll
        for (int q = 0; q < 2; q++) {
            int l4  = tid * 2 + q;
            int row = l4 >> 2;
            int c4  = (l4 & 3) << 2;
            int gm  = m0 + row; if (gm > M - 1) gm = M - 1;
            float4 v = *reinterpret_cast<const float4*>(Ab + (long)gm * lda + k0 + c4);
            As[c4 + 0][row] = v.x; As[c4 + 1][row] = v.y;
            As[c4 + 2][row] = v.z; As[c4 + 3][row] = v.w;
        }
        {
            int row = tid >> 4;
            int c4  = (tid & 15) << 2;
            float4 v = *reinterpret_cast<const float4*>(Bm + (long)(k0 + row) * N + n0 + c4);
            *reinterpret_cast<float4*>(&Bs[row][c4]) = v;
        }
        __syncthreads();
#pragma unroll
        for (int kk = 0; kk < 16; kk++) {
            float a[8], bb[4];
#pragma unroll
            for (int i = 0; i < 8; i++) a[i] = As[kk][ty * 8 + i];
#pragma unroll
            for (int j = 0; j < 4; j++) bb[j] = Bs[kk][tx * 4 + j];
#pragma unroll
            for (int i = 0; i < 8; i++)
#pragma unroll
                for (int j = 0; j < 4; j++)
                    acc[i][j] = fmaf(a[i], bb[j], acc[i][j]);
        }
        __syncthreads();
    }

#pragma unroll
    for (int i = 0; i < 8; i++) {
        int gm = m0 + ty * 8 + i;
        if (gm < M) {
#pragma unroll
            for (int j = 0; j < 4; j++) {
                int gn = n0 + tx * 4 + j;
                Cb[(long)gm * ldc + gn] = acc[i][j] + bias[gn];
            }
        }
    }
}

// ---------------------------------------------------------------------------
// Attention scores layer 1
__global__ void scores1_kernel(const float* __restrict__ a1)
{
    int gw   = (blockIdx.x * blockDim.x + threadIdx.x) >> 5;
    int lane = threadIdx.x & 31;
    if (gw >= BT_ * N_) return;
    int bt = gw / N_, n = gw % N_;
    const float* zr = g_z1 + ((size_t)bt * N_ + n) * HD_;
#pragma unroll
    for (int h = 0; h < H_; h++) {
        float s = 0.f, d = 0.f;
#pragma unroll
        for (int q = 0; q < 2; q++) {
            int dd = lane + 32 * q;
            float zv = zr[h * 64 + dd];
            s = fmaf(zv, a1[h * 128 + dd], s);
            d = fmaf(zv, a1[h * 128 + 64 + dd], d);
        }
#pragma unroll
        for (int o = 16; o >= 1; o >>= 1) {
            s += __shfl_xor_sync(0xffffffffu, s, o);
            d += __shfl_xor_sync(0xffffffffu, d, o);
        }
        if (lane == 0) {
            g_ssrc1[(bt * H_ + h) * N_ + n] = s;
            g_sdst1[(bt * H_ + h) * N_ + n] = d;
        }
    }
}

__global__ void scores2_kernel(const float* __restrict__ a2)
{
    int gw   = (blockIdx.x * blockDim.x + threadIdx.x) >> 5;
    int lane = threadIdx.x & 31;
    if (gw >= BT_ * N_) return;
    int bt = gw / N_, n = gw % N_;
    const float* zr = g_z2 + ((size_t)bt * N_ + n) * D2_;
    float s = 0.f, d = 0.f;
#pragma unroll
    for (int q = 0; q < 2; q++) {
        int dd = lane + 32 * q;
        float zv = zr[dd];
        s = fmaf(zv, a2[dd],      s);
        d = fmaf(zv, a2[64 + dd], d);
    }
#pragma unroll
    for (int o = 16; o >= 1; o >>= 1) {
        s += __shfl_xor_sync(0xffffffffu, s, o);
        d += __shfl_xor_sync(0xffffffffu, d, o);
    }
    if (lane == 0) { g_ssrc2[bt * N_ + n] = s; g_sdst2[bt * N_ + n] = d; }
}

// ---------------------------------------------------------------------------
// GAT attention layer 1: warp per (bt,n), 4 heads, softmax over 8 neighbors, ELU
__global__ void attn1_kernel(const int* __restrict__ src, const float* __restrict__ a1b)
{
    int gw   = (blockIdx.x * blockDim.x + threadIdx.x) >> 5;
    int lane = threadIdx.x & 31;
    if (gw >= BT_ * N_) return;
    int bt = gw / N_, n = gw % N_;

    int sk = 0;
    if (lane < 8) sk = src[n * DEG_ + lane];

#pragma unroll
    for (int h = 0; h < H_; h++) {
        float sd = g_sdst1[(bt * H_ + h) * N_ + n];
        float e = -1e30f;
        if (lane < 8) {
            float v = g_ssrc1[(bt * H_ + h) * N_ + sk] + sd + a1b[h];
            e = (v > 0.f) ? v : 0.01f * v;
        }
        float m = e;
#pragma unroll
        for (int o = 4; o >= 1; o >>= 1) m = fmaxf(m, __shfl_xor_sync(0xffffffffu, m, o, 8));
        float p = __expf(e - m);
        float sum = p;
#pragma unroll
        for (int o = 4; o >= 1; o >>= 1) sum += __shfl_xor_sync(0xffffffffu, sum, o, 8);
        float alpha = p / sum;

        float acc0 = 0.f, acc1 = 0.f;
#pragma unroll
        for (int k = 0; k < 8; k++) {
            float al = __shfl_sync(0xffffffffu, alpha, k);
            int   s2 = __shfl_sync(0xffffffffu, sk, k);
            const float* zrow = g_z1 + ((size_t)bt * N_ + s2) * HD_ + h * 64;
            acc0 = fmaf(al, zrow[lane],      acc0);
            acc1 = fmaf(al, zrow[lane + 32], acc1);
        }
        size_t o = ((size_t)bt * N_ + n) * HD_ + h * 64 + lane;
        g_h1[o]      = acc0 > 0.f ? acc0 : expm1f(acc0);
        g_h1[o + 32] = acc1 > 0.f ? acc1 : expm1f(acc1);
    }
}

// GAT attention layer 2 (single head), writes directly into xs layout [s][b][d]
__global__ void attn2_kernel(const int* __restrict__ src, const float* __restrict__ a2b)
{
    int gw   = (blockIdx.x * blockDim.x + threadIdx.x) >> 5;
    int lane = threadIdx.x & 31;
    if (gw >= BT_ * N_) return;
    int bt = gw / N_, n = gw % N_;
    int b = bt / T_, t = bt % T_;

    int sk = 0;
    if (lane < 8) sk = src[n * DEG_ + lane];

    float sd = g_sdst2[bt * N_ + n];
    float e = -1e30f;
    if (lane < 8) {
        float v = g_ssrc2[bt * N_ + sk] + sd + a2b[0];
        e = (v > 0.f) ? v : 0.01f * v;
    }
    float m = e;
#pragma unroll
    for (int o = 4; o >= 1; o >>= 1) m = fmaxf(m, __shfl_xor_sync(0xffffffffu, m, o, 8));
    float p = __expf(e - m);
    float sum = p;
#pragma unroll
    for (int o = 4; o >= 1; o >>= 1) sum += __shfl_xor_sync(0xffffffffu, sum, o, 8);
    float alpha = p / sum;

    float acc0 = 0.f, acc1 = 0.f;
#pragma unroll
    for (int k = 0; k < 8; k++) {
        float al = __shfl_sync(0xffffffffu, alpha, k);
        int   s2 = __shfl_sync(0xffffffffu, sk, k);
        const float* zrow = g_z2 + ((size_t)bt * N_ + s2) * D2_;
        acc0 = fmaf(al, zrow[lane],      acc0);
        acc1 = fmaf(al, zrow[lane + 32], acc1);
    }
    int srow = (n * T_ + t) * B_ + b;
    size_t o = (size_t)srow * D2_ + lane;
    g_seqT[o]      = acc0 > 0.f ? acc0 : expm1f(acc0);
    g_seqT[o + 32] = acc1 > 0.f ? acc1 : expm1f(acc1);
}

// ---------------------------------------------------------------------------
// GRU scan v4: v2 topology, fat removed.
// 8 blocks (one per chain), 384 threads (12 warps).
// thread t -> (j = t>>1, half = t&1): half of the 64-wide dot for gate-row j
// (j in [0,192)).  shfl_xor(1) combines halves; even lanes store sB[j].
// Gate lanes = even t < 128 (warps 0-3), unit gj = t>>1 in [0,64):
//   load own gi (3 values, walking prefetch, 4 deep), rcp.approx sigmoids,
//   tanh(y) = 2*sigma(2y)-1, h_u carried in register (gate lane is sole
//   writer of h_sh[gj]).  2 bars/step (dot->gates, gates->next dot).
template <bool STORE>
__device__ __forceinline__ void gru_step4(
    float* __restrict__ h_sh, float* __restrict__ sB,
    const float* __restrict__ w, float* q3,        // q3: this step's 3 gi values
    const float* __restrict__ pf, int gj,          // prefetch base for step s+4
    float bh0, float bh1, float bh2,
    float& h_u, int half, int j, bool gate, int b, int st)
{
    // kick next prefetch first (overlap DRAM latency with the dot)
    float p0 = 0.f, p1 = 0.f, p2 = 0.f;
    if (gate) {
        p0 = __ldg(pf + gj);
        p1 = __ldg(pf + 64 + gj);
        p2 = __ldg(pf + 128 + gj);
    }

    // half-dot: 32 MACs against h_sh[half*32 ..]
    const float4* h4 = reinterpret_cast<const float4*>(h_sh + half * 32);
    float a0 = 0.f, a1 = 0.f, a2 = 0.f, a3 = 0.f;
#pragma unroll
    for (int k = 0; k < 8; k++) {
        float4 hv = h4[k];
        a0 = fmaf(w[4 * k + 0], hv.x, a0);
        a1 = fmaf(w[4 * k + 1], hv.y, a1);
        a2 = fmaf(w[4 * k + 2], hv.z, a2);
        a3 = fmaf(w[4 * k + 3], hv.w, a3);
    }
    float part = (a0 + a1) + (a2 + a3);
    part += __shfl_xor_sync(0xffffffffu, part, 1);
    if (half == 0) sB[j] = part;
    __syncthreads();                                // dot results visible

    if (gate) {
        float r  = sigmoid_fast(q3[0] + sB[gj]      + bh0);
        float z  = sigmoid_fast(q3[1] + sB[64 + gj] + bh1);
        float y  = fmaf(r, sB[128 + gj] + bh2, q3[2]);
        float nn = fmaf(2.f, sigmoid_fast(2.f * y), -1.f);   // tanh(y)
        float hn = fmaf(z, h_u - nn, nn);           // (1-z)*n + z*h
        h_sh[gj] = hn;
        h_u = hn;
        if (STORE)
            g_hloc[((size_t)(st >> 3) * B_ + b) * G_ + gj] = hn;
    }
    q3[0] = p0; q3[1] = p1; q3[2] = p2;
    __syncthreads();                                // h updated for next dot
}

__global__ void __launch_bounds__(384, 1)
gru_scan(const float* __restrict__ gi, const float* __restrict__ h0,
         const float* __restrict__ Whh, const float* __restrict__ bhh)
{
    const int b    = blockIdx.x;
    const int t    = threadIdx.x;
    const int j    = t >> 1;                 // gate-row 0..191
    const int half = t & 1;
    const bool gate = (t < 128) && (half == 0);
    const int gj   = j;                      // valid as unit index when gate

    float w[32];
#pragma unroll
    for (int k = 0; k < 32; k++) w[k] = Whh[(size_t)j * 64 + half * 32 + k];

    // gate-lane constants
    float bh0 = 0.f, bh1 = 0.f, bh2 = 0.f, h_u = 0.f;
    if (gate) {
        bh0 = bhh[gj];
        bh1 = bhh[64 + gj];
        bh2 = bhh[128 + gj];
        h_u = h0[b * 64 + gj];
    }

    __shared__ __align__(16) float h_sh[64];
    __shared__ float sB[192];
    if (t < 64) h_sh[t] = h0[b * 64 + t];
    __syncthreads();

    const long STRIDE = (long)B_ * 192;      // 1536 floats/step
    const float* gbase = gi + (long)b * 192;

    float q[4][3];
    if (gate) {
#pragma unroll
        for (int i = 0; i < 4; i++) {
            q[i][0] = __ldg(gbase + (long)i * STRIDE + gj);
            q[i][1] = __ldg(gbase + (long)i * STRIDE + 64 + gj);
            q[i][2] = __ldg(gbase + (long)i * STRIDE + 128 + gj);
        }
    }
    const float* pf = gbase + 4 * STRIDE;    // walking prefetch base (padded tail)

    for (int s = 0; s < SEQ_; s += 4) {
        gru_step4<false>(h_sh, sB, w, q[0], pf,              gj, bh0, bh1, bh2, h_u, half, j, gate, b, s);
        gru_step4<false>(h_sh, sB, w, q[1], pf + STRIDE,     gj, bh0, bh1, bh2, h_u, half, j, gate, b, s + 1);
        gru_step4<false>(h_sh, sB, w, q[2], pf + 2 * STRIDE, gj, bh0, bh1, bh2, h_u, half, j, gate, b, s + 2);
        if ((s & 7) == 4)
            gru_step4<true >(h_sh, sB, w, q[3], pf + 3 * STRIDE, gj, bh0, bh1, bh2, h_u, half, j, gate, b, s + 3);
        else
            gru_step4<false>(h_sh, sB, w, q[3], pf + 3 * STRIDE, gj, bh0, bh1, bh2, h_u, half, j, gate, b, s + 3);
        pf += 4 * STRIDE;
    }
}

// ---------------------------------------------------------------------------
// Output projection: out[b][n][p] = h_loc[n][b][:] . Wp[:,p] + bp[p]
__global__ void proj_kernel(const float* __restrict__ Wp, const float* __restrict__ bp,
                            float* __restrict__ out)
{
    int gw   = (blockIdx.x * blockDim.x + threadIdx.x) >> 5;
    int lane = threadIdx.x & 31;
    if (gw >= B_ * N_) return;
    int b = gw / N_, n = gw % N_;
    if (lane < PW_) {
        const float* hl = g_hloc + ((size_t)n * B_ + b) * G_;
        float acc = bp[lane];
#pragma unroll
        for (int g = 0; g < G_; g++) acc = fmaf(hl[g], Wp[g * PW_ + lane], acc);
        out[((size_t)b * N_ + n) * PW_ + lane] = acc;
    }
}

// ---------------------------------------------------------------------------
extern "C" void kernel_launch(void* const* d_in, const int* in_sizes, int n_in,
                              void* d_out, int out_size)
{
    const float* dynamic = (const float*)d_in[0];
    const float* h0      = (const float*)d_in[1];
    const int*   src     = (const int*)  d_in[2];
    const float* W1      = (const float*)d_in[3];
    const float* b1      = (const float*)d_in[4];
    const float* a1      = (const float*)d_in[5];
    const float* a1b     = (const float*)d_in[6];
    const float* W2      = (const float*)d_in[7];
    const float* b2      = (const float*)d_in[8];
    const float* a2      = (const float*)d_in[9];
    const float* a2b     = (const float*)d_in[10];
    const float* Wih     = (const float*)d_in[11];
    const float* Whh     = (const float*)d_in[12];
    const float* bih     = (const float*)d_in[13];
    const float* bhh     = (const float*)d_in[14];
    const float* Wp      = (const float*)d_in[15];
    const float* bp      = (const float*)d_in[16];
    float* out = (float*)d_out;

    float *z1p, *h1p, *z2p, *seqTp, *gip, *W1catp, *WihTp;
    cudaGetSymbolAddress((void**)&z1p,    g_z1);
    cudaGetSymbolAddress((void**)&h1p,    g_h1);
    cudaGetSymbolAddress((void**)&z2p,    g_z2);
    cudaGetSymbolAddress((void**)&seqTp,  g_seqT);
    cudaGetSymbolAddress((void**)&gip,    g_gi);
    cudaGetSymbolAddress((void**)&W1catp, g_W1cat);
    cudaGetSymbolAddress((void**)&WihTp,  g_WihT);

    // 0) pack weights
    pack_kernel<<<128, 256>>>(W1, Wih);

    // 1) z1 = x @ W1cat + b1   (per (b,t): 2000x128 @ 128x256)
    gemm_bias<<<dim3(16, 4, BT_), 256>>>(dynamic, W1catp, b1, z1p,
                                         N_, HD_, F_, T_ * F_, HD_,
                                         (long)N_ * T_ * F_, (long)F_, T_,
                                         (long)N_ * HD_);
    // 2) attention scores + aggregation layer 1 -> h1 (ELU)
    scores1_kernel<<<16000, 256>>>(a1);
    attn1_kernel<<<16000, 256>>>(src, a1b);

    // 3) z2 = h1 @ W2 + b2   (per (b,t): 2000x256 @ 256x64)
    gemm_bias<<<dim3(16, 1, BT_), 256>>>(h1p, W2, b2, z2p,
                                         N_, D2_, HD_, HD_, D2_,
                                         (long)N_ * HD_, 0L, 1,
                                         (long)N_ * D2_);
    // 4) attention layer 2 -> seqT (xs layout), ELU
    scores2_kernel<<<16000, 256>>>(a2);
    attn2_kernel<<<16000, 256>>>(src, a2b);

    // 5) gi = seqT @ WihT + bih   (128000x64 @ 64x192)
    gemm_bias<<<dim3(1000, 3, 1), 256>>>(seqTp, WihTp, bih, gip,
                                         SEQ_ * B_, 3 * G_, D2_, D2_, 3 * G_,
                                         0L, 0L, 1, 0L);

    // 6) sequential GRU scan (8 independent chains) — v4
    gru_scan<<<B_, 384>>>(gip, h0, Whh, bhh);

    // 7) projection
    proj_kernel<<<2000, 256>>>(Wp, bp, out);
}